// round 12
// baseline (speedup 1.0000x reference)
#include <cuda_runtime.h>
#include <cuda_fp16.h>
#include <math.h>
#include <stdint.h>

#define N_NODES 10000
#define N_EDGES 5000
#define M_PAIRS 200000
#define DIM 128
#define KCAPS 8
#define FOLD_LEN 10000   // M / NFOLD
#define NSPLIT 8
#define EPS 1e-12f

// GEMM tiling (fp16 single-pass)
#define BM 64
#define BK 64
#define TILES 157            // ceil(10000/64)
#define RSA 72               // A smem row stride (fp16), padded
#define RSB 136              // B smem row stride (fp16), padded
#define STAGE_ELEMS (BM*RSA + BK*RSB)          // 13312 fp16 per stage
#define GEMM_SMEM_BYTES (2 * STAGE_ELEMS * 2)  // 53248 B -> 2 CTAs/SM

// ---------------- scratch (static device globals; no allocation) ----------------
__device__ float  g_xn[N_NODES * DIM];                // capnormed x (fp32)
__device__ __half g_xh[N_NODES * DIM];                // capnormed x (fp16)
__device__ float  g_gpart[NSPLIT][N_EDGES * DIM];     // split-K GEMM partials
__device__ float  g_uedge[N_EDGES * DIM];             // routing1 result

__device__ int  g_cntE[N_EDGES],  g_startE[N_EDGES + 1],  g_wptrE[N_EDGES];
__device__ int  g_cntN[N_NODES],  g_startN[N_NODES + 1],  g_wptrN[N_NODES];
__device__ int2 g_tmpE[M_PAIRS],  g_itemsE[M_PAIRS];
__device__ int2 g_tmpN[M_PAIRS],  g_itemsN[M_PAIRS];

// ---------------- small helpers ----------------
__device__ __forceinline__ unsigned pack_h2(__half lo, __half hi) {
    return ((unsigned)__half_as_ushort(hi) << 16) | (unsigned)__half_as_ushort(lo);
}
__device__ __forceinline__ void ldsm_x4(unsigned* r, unsigned addr) {
    asm volatile("ldmatrix.sync.aligned.m8n8.x4.shared.b16 {%0,%1,%2,%3}, [%4];"
        : "=r"(r[0]), "=r"(r[1]), "=r"(r[2]), "=r"(r[3]) : "r"(addr));
}
__device__ __forceinline__ void ldsm_x4_t(unsigned* r, unsigned addr) {
    asm volatile("ldmatrix.sync.aligned.m8n8.x4.trans.shared.b16 {%0,%1,%2,%3}, [%4];"
        : "=r"(r[0]), "=r"(r[1]), "=r"(r[2]), "=r"(r[3]) : "r"(addr));
}
__device__ __forceinline__ void mma_f16(float* c, const unsigned* a, const unsigned* b) {
    asm volatile("mma.sync.aligned.m16n8k16.row.col.f32.f16.f16.f32 "
        "{%0,%1,%2,%3}, {%4,%5,%6,%7}, {%8,%9}, {%0,%1,%2,%3};"
        : "+f"(c[0]), "+f"(c[1]), "+f"(c[2]), "+f"(c[3])
        : "r"(a[0]), "r"(a[1]), "r"(a[2]), "r"(a[3]), "r"(b[0]), "r"(b[1]));
}
__device__ __forceinline__ void cp16(unsigned dst, const void* src, int pred_bytes) {
    asm volatile("cp.async.cg.shared.global [%0], [%1], 16, %2;"
        :: "r"(dst), "l"(src), "r"(pred_bytes) : "memory");
}
#define CP_COMMIT() asm volatile("cp.async.commit_group;" ::: "memory")
#define CP_WAIT0()  asm volatile("cp.async.wait_group 0;" ::: "memory")

// ---------------- capnorm x -> g_xn (fp32) + g_xh (fp16) ----------------
__global__ void capnorm_k(const float* __restrict__ in) {
    if (!in) return;                                   // warmup guard
    int idx = blockIdx.x * blockDim.x + threadIdx.x;   // (row, group of 16)
    if (idx >= N_NODES * KCAPS) return;
    const float4* p = (const float4*)(in + (size_t)idx * 16);
    float v[16];
    #pragma unroll
    for (int q = 0; q < 4; q++) {
        float4 t = p[q];
        v[q*4+0]=t.x; v[q*4+1]=t.y; v[q*4+2]=t.z; v[q*4+3]=t.w;
    }
    float n2 = 0.f;
    #pragma unroll
    for (int j = 0; j < 16; j++) n2 += v[j]*v[j];
    float inv = 1.0f / fmaxf(sqrtf(n2), EPS);
    #pragma unroll
    for (int j = 0; j < 16; j++) v[j] *= inv;
    float4* q4 = (float4*)(g_xn + (size_t)idx * 16);
    #pragma unroll
    for (int q = 0; q < 4; q++)
        q4[q] = make_float4(v[q*4], v[q*4+1], v[q*4+2], v[q*4+3]);
    unsigned hu[8];
    #pragma unroll
    for (int j = 0; j < 8; j++)
        hu[j] = pack_h2(__float2half_rn(v[2*j]), __float2half_rn(v[2*j+1]));
    uint4* dh = (uint4*)(g_xh + (size_t)idx * 16);
    dh[0] = make_uint4(hu[0],hu[1],hu[2],hu[3]);
    dh[1] = make_uint4(hu[4],hu[5],hu[6],hu[7]);
}

// ---------------- fp16 GEMM: A reg-staged+converted, B via cp.async ----------------
__device__ __forceinline__ void ldg_A(const float* __restrict__ A, int t, int tid,
                                      int blockRow, float4* a) {
    int arow = blockRow + (tid >> 2);
    int akc  = (tid & 3) * 16;
    int k0   = t * BK;
    const float* base = A + (size_t)arow * N_NODES;
    #pragma unroll
    for (int i = 0; i < 4; i++) {
        int kk = k0 + akc + i * 4;
        a[i] = (arow < N_EDGES && kk + 4 <= N_NODES)
             ? *(const float4*)(base + kk) : make_float4(0,0,0,0);
    }
}

__device__ __forceinline__ void sts_A(__half* stage, int tid, const float4* a) {
    float f[16];
    #pragma unroll
    for (int i = 0; i < 4; i++) {
        f[i*4+0]=a[i].x; f[i*4+1]=a[i].y; f[i*4+2]=a[i].z; f[i*4+3]=a[i].w;
    }
    unsigned hu[8];
    #pragma unroll
    for (int i = 0; i < 8; i++)
        hu[i] = pack_h2(__float2half_rn(f[2*i]), __float2half_rn(f[2*i+1]));
    int ar = tid >> 2, akc = (tid & 3) * 16;
    *(uint4*)(stage + ar*RSA + akc)     = make_uint4(hu[0],hu[1],hu[2],hu[3]);
    *(uint4*)(stage + ar*RSA + akc + 8) = make_uint4(hu[4],hu[5],hu[6],hu[7]);
}

__device__ __forceinline__ void cp_B(__half* stage, int t, int tid) {
    int br = tid >> 2, bn = (tid & 3) * 32;
    int brow = t * BK + br;
    int ok = (brow < N_NODES) ? 16 : 0;
    const __half* src = g_xh + (size_t)(brow < N_NODES ? brow : 0) * DIM + bn;
    unsigned dst = (unsigned)__cvta_generic_to_shared(stage + BM*RSA + br*RSB + bn);
    #pragma unroll
    for (int i = 0; i < 4; i++)
        cp16(dst + i*16, src + i*8, ok);
}

extern __shared__ __half g_smem[];

__global__ void __launch_bounds__(256, 2) gemm_f16_k(const float* __restrict__ A) {
    if (!A) return;                                    // warmup guard (uniform)
    int tid = threadIdx.x;
    int split = blockIdx.y;
    int blockRow = blockIdx.x * BM;
    int t0 = (split * TILES) / NSPLIT;
    int t1 = ((split + 1) * TILES) / NSPLIT;

    int lane = tid & 31, wid = tid >> 5;
    int wm = wid & 1, wn = wid >> 1;          // 2 M-warps x 4 N-warps
    int m_off = wm * 32, n_off = wn * 32;

    float c[8][4];
    #pragma unroll
    for (int i = 0; i < 8; i++)
        #pragma unroll
        for (int j = 0; j < 4; j++) c[i][j] = 0.f;

    float4 areg[4];
    ldg_A(A, t0, tid, blockRow, areg);
    cp_B(g_smem, t0, tid);
    CP_COMMIT();
    sts_A(g_smem, tid, areg);
    CP_WAIT0();
    __syncthreads();

    int g = lane >> 3, rr = lane & 7;
    int aoff = ((g & 1) ? 8 : 0) + rr;
    int akx  = ((g & 2) ? 8 : 0);
    int boff = ((g & 1) ? 8 : 0) + rr;
    int bnx  = ((g & 2) ? 8 : 0);

    for (int t = t0; t < t1; t++) {
        __half* cur = g_smem + ((t - t0) & 1) * STAGE_ELEMS;
        __half* nxt = g_smem + (((t - t0) + 1) & 1) * STAGE_ELEMS;
        bool have_next = (t + 1 < t1);
        if (have_next) {
            ldg_A(A, t + 1, tid, blockRow, areg);
            cp_B(nxt, t + 1, tid);
            CP_COMMIT();
        }

        __half* As = cur;
        __half* Bs = cur + BM*RSA;

        #pragma unroll
        for (int ks = 0; ks < 4; ks++) {
            int k0 = ks * 16;
            unsigned af[2][4], bf[8];
            #pragma unroll
            for (int mf = 0; mf < 2; mf++) {
                int mrow = m_off + mf*16 + aoff;
                ldsm_x4(af[mf], (unsigned)__cvta_generic_to_shared(As + mrow*RSA + k0 + akx));
            }
            #pragma unroll
            for (int nf = 0; nf < 2; nf++) {
                int ncol = n_off + nf*16 + bnx;
                ldsm_x4_t(&bf[nf*4], (unsigned)__cvta_generic_to_shared(Bs + (k0 + boff)*RSB + ncol));
            }
            #pragma unroll
            for (int mf = 0; mf < 2; mf++) {
                #pragma unroll
                for (int j = 0; j < 4; j++) {
                    const unsigned* bb = &bf[(j >> 1)*4 + (j & 1)*2];
                    mma_f16(c[mf*4+j], af[mf], bb);
                }
            }
        }
        if (have_next) sts_A(nxt, tid, areg);
        CP_WAIT0();
        __syncthreads();
    }

    float* out = g_gpart[split];
    #pragma unroll
    for (int mf = 0; mf < 2; mf++) {
        #pragma unroll
        for (int j = 0; j < 4; j++) {
            int n  = n_off + j*8 + (lane & 3)*2;
            int r1 = blockRow + m_off + mf*16 + (lane >> 2);
            int r2 = r1 + 8;
            float* cc = c[mf*4+j];
            if (r1 < N_EDGES) *(float2*)(out + (size_t)r1*DIM + n) = make_float2(cc[0], cc[1]);
            if (r2 < N_EDGES) *(float2*)(out + (size_t)r2*DIM + n) = make_float2(cc[2], cc[3]);
        }
    }
}

// ---------------- CSR build (fused) ----------------
__global__ void zero_cnt_k() {
    int i = blockIdx.x * blockDim.x + threadIdx.x;
    if (i < N_EDGES) g_cntE[i] = 0;
    if (i < N_NODES) g_cntN[i] = 0;
}

__global__ void hist_k(const int* __restrict__ edge_es, const int* __restrict__ node_es) {
    if (!edge_es) return;                              // warmup guard
    int i = blockIdx.x * blockDim.x + threadIdx.x;
    if (i >= M_PAIRS) return;
    atomicAdd(&g_cntE[edge_es[i]], 1);
    atomicAdd(&g_cntN[node_es[i]], 1);
}

__global__ void scan_both_k(int active) {
    if (!active) return;                               // warmup guard (uniform)
    const int* cnt;  int* start;  int* wptr;  int n;
    if (blockIdx.x == 0) { cnt = g_cntE; start = g_startE; wptr = g_wptrE; n = N_EDGES; }
    else                 { cnt = g_cntN; start = g_startN; wptr = g_wptrN; n = N_NODES; }
    __shared__ int ssum[1024];
    int t = threadIdx.x;
    int CH = (n + 1023) / 1024;
    int s0 = t * CH;
    int s = 0;
    for (int i = 0; i < CH; i++) { int j = s0 + i; if (j < n) s += cnt[j]; }
    ssum[t] = s;
    __syncthreads();
    for (int off = 1; off < 1024; off <<= 1) {
        int v = (t >= off) ? ssum[t - off] : 0;
        __syncthreads();
        ssum[t] += v;
        __syncthreads();
    }
    int run = (t > 0) ? ssum[t - 1] : 0;
    for (int i = 0; i < CH; i++) {
        int j = s0 + i;
        if (j < n) { start[j] = run; wptr[j] = run; run += cnt[j]; }
    }
    if (t == 0) start[n] = M_PAIRS;
}

__global__ void scatter_both_k(const int* __restrict__ edge_es, const int* __restrict__ node_es) {
    if (!edge_es) return;                              // warmup guard
    int i = blockIdx.x * blockDim.x + threadIdx.x;
    if (i >= M_PAIRS) return;
    int e = edge_es[i], nn = node_es[i];
    int posE = atomicAdd(&g_wptrE[e], 1);
    g_tmpE[posE] = make_int2(nn, i);
    int posN = atomicAdd(&g_wptrN[nn], 1);
    g_tmpN[posN] = make_int2(e, i);
}

__global__ void reorder_both_k(int active) {
    if (!active) return;                               // warmup guard
    int warp = (blockIdx.x * blockDim.x + threadIdx.x) >> 5;
    int lane = threadIdx.x & 31;
    const int2* tmp; const int* start; int2* out; int run;
    if (warp < N_EDGES) { tmp = g_tmpE; start = g_startE; out = g_itemsE; run = warp; }
    else if (warp < N_EDGES + N_NODES) {
        tmp = g_tmpN; start = g_startN; out = g_itemsN; run = warp - N_EDGES;
    } else return;
    int s = start[run], e = start[run + 1];
    for (int i = s + lane; i < e; i += 32) {
        int2 my = tmp[i];
        int rank = 0;
        for (int j = s; j < e; j++) rank += (tmp[j].y < my.y);
        out[s + rank] = my;
    }
}

// ---------------- routing: one warp per dst row, 2-way item ILP ----------------
// MODE 1: fold = orig_pos / FOLD_LEN (items stable-sorted by y => folds monotone).
// MODE 2: fold = csr_pos / FOLD_LEN (trivially monotone).
// Items within a fold are independent given u -> process PAIRS with interleaved
// shfl/exp chains to halve effective serial latency per item.
template <int MODE, bool SUMP>
__global__ void routing_k(const float* __restrict__ uinit, const float* __restrict__ src,
                          const int* __restrict__ start, const int2* __restrict__ items,
                          float* __restrict__ out, float* __restrict__ out2, int nrows) {
    int warp = (blockIdx.x * blockDim.x + threadIdx.x) >> 5;
    int lane = threadIdx.x & 31;
    if (warp >= nrows) return;                         // nrows=0 during warmup
    int row = warp;
    const unsigned FULL = 0xFFFFFFFFu;

    float4 u;
    if (SUMP) {
        u = make_float4(0.f, 0.f, 0.f, 0.f);
        #pragma unroll
        for (int p = 0; p < NSPLIT; p++) {
            float4 t = *(const float4*)(uinit + (size_t)p * N_EDGES * DIM
                                        + (size_t)row * DIM + lane * 4);
            u.x += t.x; u.y += t.y; u.z += t.z; u.w += t.w;
        }
        float n2 = u.x*u.x + u.y*u.y + u.z*u.z + u.w*u.w;
        n2 += __shfl_xor_sync(FULL, n2, 1);
        n2 += __shfl_xor_sync(FULL, n2, 2);
        float inv = 1.0f / fmaxf(sqrtf(n2), EPS);
        u.x *= inv; u.y *= inv; u.z *= inv; u.w *= inv;
    } else {
        u = *(const float4*)(uinit + (size_t)row * DIM + lane * 4);
    }

    int s = start[row], e = start[row + 1];

    for (int iter = 0; iter < 2; iter++) {
        float4 acc = make_float4(0.f, 0.f, 0.f, 0.f);
        int curfold = -1000000;
        int2 itA = make_int2(0, 0), itB = make_int2(0, 0);
        float4 zA = make_float4(0.f,0.f,0.f,0.f), zB = zA;
        if (s < e) {
            itA = items[s];
            zA = *(const float4*)(src + (size_t)itA.x * DIM + lane * 4);
        }
        if (s + 1 < e) {
            itB = items[s + 1];
            zB = *(const float4*)(src + (size_t)itB.x * DIM + lane * 4);
        }
        int i = s;
        while (i < e) {
            int foldA = (MODE == 1) ? (itA.y / FOLD_LEN) : (i / FOLD_LEN);
            if (foldA != curfold) {
                u.x += acc.x; u.y += acc.y; u.z += acc.z; u.w += acc.w;
                acc = make_float4(0.f, 0.f, 0.f, 0.f);
                curfold = foldA;
            }
            bool pair = (i + 1 < e);
            if (pair) {
                int foldB = (MODE == 1) ? (itB.y / FOLD_LEN) : ((i + 1) / FOLD_LEN);
                pair = (foldB == foldA);
            }
            // prefetch i+2 / i+3 (off critical path)
            int2 itC = itB, itD = itB;
            float4 zC = zB, zD = zB;
            if (i + 2 < e) {
                itC = items[i + 2];
                zC = *(const float4*)(src + (size_t)itC.x * DIM + lane * 4);
            }
            if (i + 3 < e) {
                itD = items[i + 3];
                zD = *(const float4*)(src + (size_t)itD.x * DIM + lane * 4);
            }
            // interleaved chains for A and B (independent within fold)
            float dA = zA.x*u.x + zA.y*u.y + zA.z*u.z + zA.w*u.w;
            float dB = zB.x*u.x + zB.y*u.y + zB.z*u.z + zB.w*u.w;
            dA += __shfl_xor_sync(FULL, dA, 1);  dB += __shfl_xor_sync(FULL, dB, 1);
            dA += __shfl_xor_sync(FULL, dA, 2);  dB += __shfl_xor_sync(FULL, dB, 2);
            float exA = __expf(dA), exB = __expf(dB);
            float seA = exA, seB = exB;
            seA += __shfl_xor_sync(FULL, seA, 4);   seB += __shfl_xor_sync(FULL, seB, 4);
            seA += __shfl_xor_sync(FULL, seA, 8);   seB += __shfl_xor_sync(FULL, seB, 8);
            seA += __shfl_xor_sync(FULL, seA, 16);  seB += __shfl_xor_sync(FULL, seB, 16);
            float prA = __fdividef(exA, seA);
            float prB = __fdividef(exB, seB);
            acc.x += zA.x*prA; acc.y += zA.y*prA; acc.z += zA.z*prA; acc.w += zA.w*prA;
            if (pair) {
                acc.x += zB.x*prB; acc.y += zB.y*prB; acc.z += zB.z*prB; acc.w += zB.w*prB;
                itA = itC; zA = zC; itB = itD; zB = zD;
                i += 2;
            } else {
                itA = itB; zA = zB; itB = itC; zB = zC;
                i += 1;
            }
        }
        u.x += acc.x; u.y += acc.y; u.z += acc.z; u.w += acc.w;
        float n2 = u.x*u.x + u.y*u.y + u.z*u.z + u.w*u.w;
        n2 += __shfl_xor_sync(FULL, n2, 1);
        n2 += __shfl_xor_sync(FULL, n2, 2);
        float inv = 1.0f / fmaxf(sqrtf(n2), EPS);
        u.x *= inv; u.y *= inv; u.z *= inv; u.w *= inv;
    }

    *(float4*)(out + (size_t)row * DIM + lane * 4) = u;
    if (out2) *(float4*)(out2 + (size_t)row * DIM + lane * 4) = u;
}

// ---------------- pre-main warmup ----------------
static float *p_xn, *p_gpart, *p_uedge;
static int   *p_startE, *p_startN;
static int2  *p_itemsE, *p_itemsN;
static cudaStream_t s2;
static cudaEvent_t evFork, evJoin;

namespace {
struct Warmup {
    Warmup() {
        cudaGetSymbolAddress((void**)&p_xn, g_xn);
        cudaGetSymbolAddress((void**)&p_gpart, g_gpart);
        cudaGetSymbolAddress((void**)&p_uedge, g_uedge);
        cudaGetSymbolAddress((void**)&p_startE, g_startE);
        cudaGetSymbolAddress((void**)&p_startN, g_startN);
        cudaGetSymbolAddress((void**)&p_itemsE, g_itemsE);
        cudaGetSymbolAddress((void**)&p_itemsN, g_itemsN);

        cudaStreamCreateWithFlags(&s2, cudaStreamNonBlocking);
        cudaEventCreateWithFlags(&evFork, cudaEventDisableTiming);
        cudaEventCreateWithFlags(&evJoin, cudaEventDisableTiming);

        cudaFuncSetAttribute(gemm_f16_k, cudaFuncAttributeMaxDynamicSharedMemorySize,
                             GEMM_SMEM_BYTES);

        // Warm-launch every kernel with inert arguments.
        capnorm_k<<<1, 256>>>((const float*)0);
        gemm_f16_k<<<dim3(1, 1), 256, GEMM_SMEM_BYTES>>>((const float*)0);
        zero_cnt_k<<<1, 256, 0, s2>>>();
        hist_k<<<1, 256, 0, s2>>>((const int*)0, (const int*)0);
        scan_both_k<<<2, 1024, 0, s2>>>(0);
        scatter_both_k<<<1, 256, 0, s2>>>((const int*)0, (const int*)0);
        reorder_both_k<<<1, 256, 0, s2>>>(0);
        routing_k<1, true><<<1, 256>>>((const float*)0, (const float*)0, (const int*)0,
                                       (const int2*)0, (float*)0, (float*)0, 0);
        routing_k<2, false><<<1, 256>>>((const float*)0, (const float*)0, (const int*)0,
                                        (const int2*)0, (float*)0, (float*)0, 0);
        cudaDeviceSynchronize();
    }
};
static Warmup _warmup;
}

// ---------------- launch: pure kernel launches + capturable fork/join ----------------
extern "C" void kernel_launch(void* const* d_in, const int* in_sizes, int n_in,
                              void* d_out, int out_size) {
    const float* x   = (const float*)d_in[0];
    const float* adj = (const float*)d_in[1];
    const int*   en  = (const int*)d_in[2];
    const int* edge_es = en;            // edge_node[0]
    const int* node_es = en + M_PAIRS;  // edge_node[1]

    float* out_node = (float*)d_out;                       // u_node_all
    float* out_edge = out_node + (size_t)N_NODES * DIM;    // u_edge_all

    // ---- fork: CSR chain on s2, concurrent with GEMM chain ----
    cudaEventRecord(evFork, 0);
    cudaStreamWaitEvent(s2, evFork, 0);
    zero_cnt_k<<<(N_NODES + 255) / 256, 256, 0, s2>>>();
    hist_k<<<(M_PAIRS + 255) / 256, 256, 0, s2>>>(edge_es, node_es);
    scan_both_k<<<2, 1024, 0, s2>>>(1);
    scatter_both_k<<<(M_PAIRS + 255) / 256, 256, 0, s2>>>(edge_es, node_es);
    reorder_both_k<<<((N_EDGES + N_NODES) * 32 + 255) / 256, 256, 0, s2>>>(1);
    cudaEventRecord(evJoin, s2);

    // ---- main chain: capnorm -> fp16 GEMM (split-K=8) ----
    capnorm_k<<<(N_NODES * KCAPS + 255) / 256, 256>>>(x);
    dim3 ggrid((N_EDGES + BM - 1) / BM, NSPLIT);
    gemm_f16_k<<<ggrid, 256, GEMM_SMEM_BYTES>>>(adj);

    // ---- join, then routing (2-way ILP; routing1 fuses split-K sum + capnorm) ----
    cudaStreamWaitEvent(0, evJoin, 0);
    routing_k<1, true><<<(N_EDGES + 7) / 8, 256>>>(p_gpart, p_xn, p_startE, p_itemsE,
                                                   p_uedge, out_edge, N_EDGES);
    routing_k<2, false><<<(N_NODES + 7) / 8, 256>>>(p_xn, p_uedge, p_startN, p_itemsN,
                                                    out_node, (float*)0, N_NODES);
}

// round 13
// speedup vs baseline: 1.0003x; 1.0003x over previous
#include <cuda_runtime.h>
#include <cuda_fp16.h>
#include <math.h>
#include <stdint.h>

#define N_NODES 10000
#define N_EDGES 5000
#define M_PAIRS 200000
#define DIM 128
#define KCAPS 8
#define FOLD_LEN 10000   // M / NFOLD
#define NSPLIT 8
#define EPS 1e-12f

// GEMM tiling (fp16 single-pass)
#define BM 64
#define BK 64
#define TILES 157            // ceil(10000/64)
#define RSA 72               // A smem row stride (fp16), padded
#define RSB 136              // B smem row stride (fp16), padded
#define STAGE_ELEMS (BM*RSA + BK*RSB)          // 13312 fp16 per stage
#define GEMM_SMEM_BYTES (2 * STAGE_ELEMS * 2)  // 53248 B -> 2 CTAs/SM

// ---------------- scratch (static device globals; no allocation) ----------------
__device__ float  g_xn[N_NODES * DIM];                // capnormed x (fp32)
__device__ __half g_xh[N_NODES * DIM];                // capnormed x (fp16)
__device__ float  g_gpart[NSPLIT][N_EDGES * DIM];     // split-K GEMM partials
__device__ float  g_uedge[N_EDGES * DIM];             // routing1 result

__device__ int  g_cntE[N_EDGES],  g_startE[N_EDGES + 1],  g_wptrE[N_EDGES];
__device__ int  g_cntN[N_NODES],  g_startN[N_NODES + 1],  g_wptrN[N_NODES];
__device__ int2 g_tmpE[M_PAIRS],  g_itemsE[M_PAIRS];
__device__ int2 g_tmpN[M_PAIRS],  g_itemsN[M_PAIRS];

// ---------------- small helpers ----------------
__device__ __forceinline__ unsigned pack_h2(__half lo, __half hi) {
    return ((unsigned)__half_as_ushort(hi) << 16) | (unsigned)__half_as_ushort(lo);
}
__device__ __forceinline__ void ldsm_x4(unsigned* r, unsigned addr) {
    asm volatile("ldmatrix.sync.aligned.m8n8.x4.shared.b16 {%0,%1,%2,%3}, [%4];"
        : "=r"(r[0]), "=r"(r[1]), "=r"(r[2]), "=r"(r[3]) : "r"(addr));
}
__device__ __forceinline__ void ldsm_x4_t(unsigned* r, unsigned addr) {
    asm volatile("ldmatrix.sync.aligned.m8n8.x4.trans.shared.b16 {%0,%1,%2,%3}, [%4];"
        : "=r"(r[0]), "=r"(r[1]), "=r"(r[2]), "=r"(r[3]) : "r"(addr));
}
__device__ __forceinline__ void mma_f16(float* c, const unsigned* a, const unsigned* b) {
    asm volatile("mma.sync.aligned.m16n8k16.row.col.f32.f16.f16.f32 "
        "{%0,%1,%2,%3}, {%4,%5,%6,%7}, {%8,%9}, {%0,%1,%2,%3};"
        : "+f"(c[0]), "+f"(c[1]), "+f"(c[2]), "+f"(c[3])
        : "r"(a[0]), "r"(a[1]), "r"(a[2]), "r"(a[3]), "r"(b[0]), "r"(b[1]));
}
__device__ __forceinline__ void cp16(unsigned dst, const void* src, int pred_bytes) {
    asm volatile("cp.async.cg.shared.global [%0], [%1], 16, %2;"
        :: "r"(dst), "l"(src), "r"(pred_bytes) : "memory");
}
#define CP_COMMIT() asm volatile("cp.async.commit_group;" ::: "memory")
#define CP_WAIT0()  asm volatile("cp.async.wait_group 0;" ::: "memory")

// ---------------- capnorm x -> g_xn (fp32) + g_xh (fp16) ----------------
__global__ void capnorm_k(const float* __restrict__ in) {
    if (!in) return;                                   // warmup guard
    int idx = blockIdx.x * blockDim.x + threadIdx.x;   // (row, group of 16)
    if (idx >= N_NODES * KCAPS) return;
    const float4* p = (const float4*)(in + (size_t)idx * 16);
    float v[16];
    #pragma unroll
    for (int q = 0; q < 4; q++) {
        float4 t = p[q];
        v[q*4+0]=t.x; v[q*4+1]=t.y; v[q*4+2]=t.z; v[q*4+3]=t.w;
    }
    float n2 = 0.f;
    #pragma unroll
    for (int j = 0; j < 16; j++) n2 += v[j]*v[j];
    float inv = 1.0f / fmaxf(sqrtf(n2), EPS);
    #pragma unroll
    for (int j = 0; j < 16; j++) v[j] *= inv;
    float4* q4 = (float4*)(g_xn + (size_t)idx * 16);
    #pragma unroll
    for (int q = 0; q < 4; q++)
        q4[q] = make_float4(v[q*4], v[q*4+1], v[q*4+2], v[q*4+3]);
    unsigned hu[8];
    #pragma unroll
    for (int j = 0; j < 8; j++)
        hu[j] = pack_h2(__float2half_rn(v[2*j]), __float2half_rn(v[2*j+1]));
    uint4* dh = (uint4*)(g_xh + (size_t)idx * 16);
    dh[0] = make_uint4(hu[0],hu[1],hu[2],hu[3]);
    dh[1] = make_uint4(hu[4],hu[5],hu[6],hu[7]);
}

// ---------------- fp16 GEMM: A reg-staged+converted, B via cp.async ----------------
__device__ __forceinline__ void ldg_A(const float* __restrict__ A, int t, int tid,
                                      int blockRow, float4* a) {
    int arow = blockRow + (tid >> 2);
    int akc  = (tid & 3) * 16;
    int k0   = t * BK;
    const float* base = A + (size_t)arow * N_NODES;
    #pragma unroll
    for (int i = 0; i < 4; i++) {
        int kk = k0 + akc + i * 4;
        a[i] = (arow < N_EDGES && kk + 4 <= N_NODES)
             ? *(const float4*)(base + kk) : make_float4(0,0,0,0);
    }
}

__device__ __forceinline__ void sts_A(__half* stage, int tid, const float4* a) {
    float f[16];
    #pragma unroll
    for (int i = 0; i < 4; i++) {
        f[i*4+0]=a[i].x; f[i*4+1]=a[i].y; f[i*4+2]=a[i].z; f[i*4+3]=a[i].w;
    }
    unsigned hu[8];
    #pragma unroll
    for (int i = 0; i < 8; i++)
        hu[i] = pack_h2(__float2half_rn(f[2*i]), __float2half_rn(f[2*i+1]));
    int ar = tid >> 2, akc = (tid & 3) * 16;
    *(uint4*)(stage + ar*RSA + akc)     = make_uint4(hu[0],hu[1],hu[2],hu[3]);
    *(uint4*)(stage + ar*RSA + akc + 8) = make_uint4(hu[4],hu[5],hu[6],hu[7]);
}

__device__ __forceinline__ void cp_B(__half* stage, int t, int tid) {
    int br = tid >> 2, bn = (tid & 3) * 32;
    int brow = t * BK + br;
    int ok = (brow < N_NODES) ? 16 : 0;
    const __half* src = g_xh + (size_t)(brow < N_NODES ? brow : 0) * DIM + bn;
    unsigned dst = (unsigned)__cvta_generic_to_shared(stage + BM*RSA + br*RSB + bn);
    #pragma unroll
    for (int i = 0; i < 4; i++)
        cp16(dst + i*16, src + i*8, ok);
}

extern __shared__ __half g_smem[];

__global__ void __launch_bounds__(256, 2) gemm_f16_k(const float* __restrict__ A) {
    if (!A) return;                                    // warmup guard (uniform)
    int tid = threadIdx.x;
    int split = blockIdx.y;
    int blockRow = blockIdx.x * BM;
    int t0 = (split * TILES) / NSPLIT;
    int t1 = ((split + 1) * TILES) / NSPLIT;

    int lane = tid & 31, wid = tid >> 5;
    int wm = wid & 1, wn = wid >> 1;          // 2 M-warps x 4 N-warps
    int m_off = wm * 32, n_off = wn * 32;

    float c[8][4];
    #pragma unroll
    for (int i = 0; i < 8; i++)
        #pragma unroll
        for (int j = 0; j < 4; j++) c[i][j] = 0.f;

    float4 areg[4];
    ldg_A(A, t0, tid, blockRow, areg);
    cp_B(g_smem, t0, tid);
    CP_COMMIT();
    sts_A(g_smem, tid, areg);
    CP_WAIT0();
    __syncthreads();

    int g = lane >> 3, rr = lane & 7;
    int aoff = ((g & 1) ? 8 : 0) + rr;
    int akx  = ((g & 2) ? 8 : 0);
    int boff = ((g & 1) ? 8 : 0) + rr;
    int bnx  = ((g & 2) ? 8 : 0);

    for (int t = t0; t < t1; t++) {
        __half* cur = g_smem + ((t - t0) & 1) * STAGE_ELEMS;
        __half* nxt = g_smem + (((t - t0) + 1) & 1) * STAGE_ELEMS;
        bool have_next = (t + 1 < t1);
        if (have_next) {
            ldg_A(A, t + 1, tid, blockRow, areg);
            cp_B(nxt, t + 1, tid);
            CP_COMMIT();
        }

        __half* As = cur;
        __half* Bs = cur + BM*RSA;

        #pragma unroll
        for (int ks = 0; ks < 4; ks++) {
            int k0 = ks * 16;
            unsigned af[2][4], bf[8];
            #pragma unroll
            for (int mf = 0; mf < 2; mf++) {
                int mrow = m_off + mf*16 + aoff;
                ldsm_x4(af[mf], (unsigned)__cvta_generic_to_shared(As + mrow*RSA + k0 + akx));
            }
            #pragma unroll
            for (int nf = 0; nf < 2; nf++) {
                int ncol = n_off + nf*16 + bnx;
                ldsm_x4_t(&bf[nf*4], (unsigned)__cvta_generic_to_shared(Bs + (k0 + boff)*RSB + ncol));
            }
            #pragma unroll
            for (int mf = 0; mf < 2; mf++) {
                #pragma unroll
                for (int j = 0; j < 4; j++) {
                    const unsigned* bb = &bf[(j >> 1)*4 + (j & 1)*2];
                    mma_f16(c[mf*4+j], af[mf], bb);
                }
            }
        }
        if (have_next) sts_A(nxt, tid, areg);
        CP_WAIT0();
        __syncthreads();
    }

    float* out = g_gpart[split];
    #pragma unroll
    for (int mf = 0; mf < 2; mf++) {
        #pragma unroll
        for (int j = 0; j < 4; j++) {
            int n  = n_off + j*8 + (lane & 3)*2;
            int r1 = blockRow + m_off + mf*16 + (lane >> 2);
            int r2 = r1 + 8;
            float* cc = c[mf*4+j];
            if (r1 < N_EDGES) *(float2*)(out + (size_t)r1*DIM + n) = make_float2(cc[0], cc[1]);
            if (r2 < N_EDGES) *(float2*)(out + (size_t)r2*DIM + n) = make_float2(cc[2], cc[3]);
        }
    }
}

// ---------------- CSR build (fused) ----------------
__global__ void zero_cnt_k() {
    int i = blockIdx.x * blockDim.x + threadIdx.x;
    if (i < N_EDGES) g_cntE[i] = 0;
    if (i < N_NODES) g_cntN[i] = 0;
}

__global__ void hist_k(const int* __restrict__ edge_es, const int* __restrict__ node_es) {
    if (!edge_es) return;                              // warmup guard
    int i = blockIdx.x * blockDim.x + threadIdx.x;
    if (i >= M_PAIRS) return;
    atomicAdd(&g_cntE[edge_es[i]], 1);
    atomicAdd(&g_cntN[node_es[i]], 1);
}

__global__ void scan_both_k(int active) {
    if (!active) return;                               // warmup guard (uniform)
    const int* cnt;  int* start;  int* wptr;  int n;
    if (blockIdx.x == 0) { cnt = g_cntE; start = g_startE; wptr = g_wptrE; n = N_EDGES; }
    else                 { cnt = g_cntN; start = g_startN; wptr = g_wptrN; n = N_NODES; }
    __shared__ int ssum[1024];
    int t = threadIdx.x;
    int CH = (n + 1023) / 1024;
    int s0 = t * CH;
    int s = 0;
    for (int i = 0; i < CH; i++) { int j = s0 + i; if (j < n) s += cnt[j]; }
    ssum[t] = s;
    __syncthreads();
    for (int off = 1; off < 1024; off <<= 1) {
        int v = (t >= off) ? ssum[t - off] : 0;
        __syncthreads();
        ssum[t] += v;
        __syncthreads();
    }
    int run = (t > 0) ? ssum[t - 1] : 0;
    for (int i = 0; i < CH; i++) {
        int j = s0 + i;
        if (j < n) { start[j] = run; wptr[j] = run; run += cnt[j]; }
    }
    if (t == 0) start[n] = M_PAIRS;
}

__global__ void scatter_both_k(const int* __restrict__ edge_es, const int* __restrict__ node_es) {
    if (!edge_es) return;                              // warmup guard
    int i = blockIdx.x * blockDim.x + threadIdx.x;
    if (i >= M_PAIRS) return;
    int e = edge_es[i], nn = node_es[i];
    int posE = atomicAdd(&g_wptrE[e], 1);
    g_tmpE[posE] = make_int2(nn, i);
    int posN = atomicAdd(&g_wptrN[nn], 1);
    g_tmpN[posN] = make_int2(e, i);
}

__global__ void reorder_both_k(int active) {
    if (!active) return;                               // warmup guard
    int warp = (blockIdx.x * blockDim.x + threadIdx.x) >> 5;
    int lane = threadIdx.x & 31;
    const int2* tmp; const int* start; int2* out; int run;
    if (warp < N_EDGES) { tmp = g_tmpE; start = g_startE; out = g_itemsE; run = warp; }
    else if (warp < N_EDGES + N_NODES) {
        tmp = g_tmpN; start = g_startN; out = g_itemsN; run = warp - N_EDGES;
    } else return;
    int s = start[run], e = start[run + 1];
    for (int i = s + lane; i < e; i += 32) {
        int2 my = tmp[i];
        int rank = 0;
        for (int j = s; j < e; j++) rank += (tmp[j].y < my.y);
        out[s + rank] = my;
    }
}

// ---------------- routing: one warp per dst row, 2-way item ILP ----------------
// MODE 1: fold = orig_pos / FOLD_LEN (items stable-sorted by y => folds monotone).
// MODE 2: fold = csr_pos / FOLD_LEN (trivially monotone).
// Items within a fold are independent given u -> process PAIRS with interleaved
// shfl/exp chains to halve effective serial latency per item.
template <int MODE, bool SUMP>
__global__ void routing_k(const float* __restrict__ uinit, const float* __restrict__ src,
                          const int* __restrict__ start, const int2* __restrict__ items,
                          float* __restrict__ out, float* __restrict__ out2, int nrows) {
    int warp = (blockIdx.x * blockDim.x + threadIdx.x) >> 5;
    int lane = threadIdx.x & 31;
    if (warp >= nrows) return;                         // nrows=0 during warmup
    int row = warp;
    const unsigned FULL = 0xFFFFFFFFu;

    float4 u;
    if (SUMP) {
        u = make_float4(0.f, 0.f, 0.f, 0.f);
        #pragma unroll
        for (int p = 0; p < NSPLIT; p++) {
            float4 t = *(const float4*)(uinit + (size_t)p * N_EDGES * DIM
                                        + (size_t)row * DIM + lane * 4);
            u.x += t.x; u.y += t.y; u.z += t.z; u.w += t.w;
        }
        float n2 = u.x*u.x + u.y*u.y + u.z*u.z + u.w*u.w;
        n2 += __shfl_xor_sync(FULL, n2, 1);
        n2 += __shfl_xor_sync(FULL, n2, 2);
        float inv = 1.0f / fmaxf(sqrtf(n2), EPS);
        u.x *= inv; u.y *= inv; u.z *= inv; u.w *= inv;
    } else {
        u = *(const float4*)(uinit + (size_t)row * DIM + lane * 4);
    }

    int s = start[row], e = start[row + 1];

    for (int iter = 0; iter < 2; iter++) {
        float4 acc = make_float4(0.f, 0.f, 0.f, 0.f);
        int curfold = -1000000;
        int2 itA = make_int2(0, 0), itB = make_int2(0, 0);
        float4 zA = make_float4(0.f,0.f,0.f,0.f), zB = zA;
        if (s < e) {
            itA = items[s];
            zA = *(const float4*)(src + (size_t)itA.x * DIM + lane * 4);
        }
        if (s + 1 < e) {
            itB = items[s + 1];
            zB = *(const float4*)(src + (size_t)itB.x * DIM + lane * 4);
        }
        int i = s;
        while (i < e) {
            int foldA = (MODE == 1) ? (itA.y / FOLD_LEN) : (i / FOLD_LEN);
            if (foldA != curfold) {
                u.x += acc.x; u.y += acc.y; u.z += acc.z; u.w += acc.w;
                acc = make_float4(0.f, 0.f, 0.f, 0.f);
                curfold = foldA;
            }
            bool pair = (i + 1 < e);
            if (pair) {
                int foldB = (MODE == 1) ? (itB.y / FOLD_LEN) : ((i + 1) / FOLD_LEN);
                pair = (foldB == foldA);
            }
            // prefetch i+2 / i+3 (off critical path)
            int2 itC = itB, itD = itB;
            float4 zC = zB, zD = zB;
            if (i + 2 < e) {
                itC = items[i + 2];
                zC = *(const float4*)(src + (size_t)itC.x * DIM + lane * 4);
            }
            if (i + 3 < e) {
                itD = items[i + 3];
                zD = *(const float4*)(src + (size_t)itD.x * DIM + lane * 4);
            }
            // interleaved chains for A and B (independent within fold)
            float dA = zA.x*u.x + zA.y*u.y + zA.z*u.z + zA.w*u.w;
            float dB = zB.x*u.x + zB.y*u.y + zB.z*u.z + zB.w*u.w;
            dA += __shfl_xor_sync(FULL, dA, 1);  dB += __shfl_xor_sync(FULL, dB, 1);
            dA += __shfl_xor_sync(FULL, dA, 2);  dB += __shfl_xor_sync(FULL, dB, 2);
            float exA = __expf(dA), exB = __expf(dB);
            float seA = exA, seB = exB;
            seA += __shfl_xor_sync(FULL, seA, 4);   seB += __shfl_xor_sync(FULL, seB, 4);
            seA += __shfl_xor_sync(FULL, seA, 8);   seB += __shfl_xor_sync(FULL, seB, 8);
            seA += __shfl_xor_sync(FULL, seA, 16);  seB += __shfl_xor_sync(FULL, seB, 16);
            float prA = __fdividef(exA, seA);
            float prB = __fdividef(exB, seB);
            acc.x += zA.x*prA; acc.y += zA.y*prA; acc.z += zA.z*prA; acc.w += zA.w*prA;
            if (pair) {
                acc.x += zB.x*prB; acc.y += zB.y*prB; acc.z += zB.z*prB; acc.w += zB.w*prB;
                itA = itC; zA = zC; itB = itD; zB = zD;
                i += 2;
            } else {
                itA = itB; zA = zB; itB = itC; zB = zC;
                i += 1;
            }
        }
        u.x += acc.x; u.y += acc.y; u.z += acc.z; u.w += acc.w;
        float n2 = u.x*u.x + u.y*u.y + u.z*u.z + u.w*u.w;
        n2 += __shfl_xor_sync(FULL, n2, 1);
        n2 += __shfl_xor_sync(FULL, n2, 2);
        float inv = 1.0f / fmaxf(sqrtf(n2), EPS);
        u.x *= inv; u.y *= inv; u.z *= inv; u.w *= inv;
    }

    *(float4*)(out + (size_t)row * DIM + lane * 4) = u;
    if (out2) *(float4*)(out2 + (size_t)row * DIM + lane * 4) = u;
}

// ---------------- pre-main warmup ----------------
static float *p_xn, *p_gpart, *p_uedge;
static int   *p_startE, *p_startN;
static int2  *p_itemsE, *p_itemsN;
static cudaStream_t s2;
static cudaEvent_t evFork, evJoin;

namespace {
struct Warmup {
    Warmup() {
        cudaGetSymbolAddress((void**)&p_xn, g_xn);
        cudaGetSymbolAddress((void**)&p_gpart, g_gpart);
        cudaGetSymbolAddress((void**)&p_uedge, g_uedge);
        cudaGetSymbolAddress((void**)&p_startE, g_startE);
        cudaGetSymbolAddress((void**)&p_startN, g_startN);
        cudaGetSymbolAddress((void**)&p_itemsE, g_itemsE);
        cudaGetSymbolAddress((void**)&p_itemsN, g_itemsN);

        cudaStreamCreateWithFlags(&s2, cudaStreamNonBlocking);
        cudaEventCreateWithFlags(&evFork, cudaEventDisableTiming);
        cudaEventCreateWithFlags(&evJoin, cudaEventDisableTiming);

        cudaFuncSetAttribute(gemm_f16_k, cudaFuncAttributeMaxDynamicSharedMemorySize,
                             GEMM_SMEM_BYTES);

        // Warm-launch every kernel with inert arguments.
        capnorm_k<<<1, 256>>>((const float*)0);
        gemm_f16_k<<<dim3(1, 1), 256, GEMM_SMEM_BYTES>>>((const float*)0);
        zero_cnt_k<<<1, 256, 0, s2>>>();
        hist_k<<<1, 256, 0, s2>>>((const int*)0, (const int*)0);
        scan_both_k<<<2, 1024, 0, s2>>>(0);
        scatter_both_k<<<1, 256, 0, s2>>>((const int*)0, (const int*)0);
        reorder_both_k<<<1, 256, 0, s2>>>(0);
        routing_k<1, true><<<1, 256>>>((const float*)0, (const float*)0, (const int*)0,
                                       (const int2*)0, (float*)0, (float*)0, 0);
        routing_k<2, false><<<1, 256>>>((const float*)0, (const float*)0, (const int*)0,
                                        (const int2*)0, (float*)0, (float*)0, 0);
        cudaDeviceSynchronize();
    }
};
static Warmup _warmup;
}

// ---------------- launch: pure kernel launches + capturable fork/join ----------------
extern "C" void kernel_launch(void* const* d_in, const int* in_sizes, int n_in,
                              void* d_out, int out_size) {
    const float* x   = (const float*)d_in[0];
    const float* adj = (const float*)d_in[1];
    const int*   en  = (const int*)d_in[2];
    const int* edge_es = en;            // edge_node[0]
    const int* node_es = en + M_PAIRS;  // edge_node[1]

    float* out_node = (float*)d_out;                       // u_node_all
    float* out_edge = out_node + (size_t)N_NODES * DIM;    // u_edge_all

    // ---- fork: CSR chain on s2, concurrent with GEMM chain ----
    cudaEventRecord(evFork, 0);
    cudaStreamWaitEvent(s2, evFork, 0);
    zero_cnt_k<<<(N_NODES + 255) / 256, 256, 0, s2>>>();
    hist_k<<<(M_PAIRS + 255) / 256, 256, 0, s2>>>(edge_es, node_es);
    scan_both_k<<<2, 1024, 0, s2>>>(1);
    scatter_both_k<<<(M_PAIRS + 255) / 256, 256, 0, s2>>>(edge_es, node_es);
    reorder_both_k<<<((N_EDGES + N_NODES) * 32 + 255) / 256, 256, 0, s2>>>(1);
    cudaEventRecord(evJoin, s2);

    // ---- main chain: capnorm -> fp16 GEMM (split-K=8) ----
    capnorm_k<<<(N_NODES * KCAPS + 255) / 256, 256>>>(x);
    dim3 ggrid((N_EDGES + BM - 1) / BM, NSPLIT);
    gemm_f16_k<<<ggrid, 256, GEMM_SMEM_BYTES>>>(adj);

    // ---- join, then routing (2-way ILP; routing1 fuses split-K sum + capnorm) ----
    cudaStreamWaitEvent(0, evJoin, 0);
    routing_k<1, true><<<(N_EDGES + 7) / 8, 256>>>(p_gpart, p_xn, p_startE, p_itemsE,
                                                   p_uedge, out_edge, N_EDGES);
    routing_k<2, false><<<(N_NODES + 7) / 8, 256>>>(p_xn, p_uedge, p_startN, p_itemsN,
                                                    out_node, (float*)0, N_NODES);
}

// round 14
// speedup vs baseline: 1.1222x; 1.1219x over previous
#include <cuda_runtime.h>
#include <cuda_fp16.h>
#include <math.h>
#include <stdint.h>

#define N_NODES 10000
#define N_EDGES 5000
#define M_PAIRS 200000
#define DIM 128
#define KCAPS 8
#define FOLD_LEN 10000   // M / NFOLD
#define NSPLIT 7         // 79 row-blocks x 7 = 553 CTAs: 296+257 = 2 clean waves
#define EPS 1e-12f

// GEMM tiling (fp16 single-pass)
#define BM 64
#define BK 64
#define TILES 157            // ceil(10000/64)
#define RSA 72               // A smem row stride (fp16), padded
#define RSB 136              // B smem row stride (fp16), padded
#define STAGE_ELEMS (BM*RSA + BK*RSB)          // 13312 fp16 per stage
#define GEMM_SMEM_BYTES (2 * STAGE_ELEMS * 2)  // 53248 B -> 2 CTAs/SM

// ---------------- scratch (static device globals; no allocation) ----------------
__device__ float  g_xn[N_NODES * DIM];                // capnormed x (fp32)
__device__ __half g_xh[N_NODES * DIM];                // capnormed x (fp16)
__device__ float  g_gpart[NSPLIT][N_EDGES * DIM];     // split-K GEMM partials
__device__ float  g_uedge[N_EDGES * DIM];             // routing1 result

__device__ int  g_cntE[N_EDGES],  g_startE[N_EDGES + 1],  g_wptrE[N_EDGES];
__device__ int  g_cntN[N_NODES],  g_startN[N_NODES + 1],  g_wptrN[N_NODES];
__device__ int2 g_tmpE[M_PAIRS],  g_itemsE[M_PAIRS];
__device__ int2 g_tmpN[M_PAIRS],  g_itemsN[M_PAIRS];

// ---------------- small helpers ----------------
__device__ __forceinline__ unsigned pack_h2(__half lo, __half hi) {
    return ((unsigned)__half_as_ushort(hi) << 16) | (unsigned)__half_as_ushort(lo);
}
__device__ __forceinline__ void ldsm_x4(unsigned* r, unsigned addr) {
    asm volatile("ldmatrix.sync.aligned.m8n8.x4.shared.b16 {%0,%1,%2,%3}, [%4];"
        : "=r"(r[0]), "=r"(r[1]), "=r"(r[2]), "=r"(r[3]) : "r"(addr));
}
__device__ __forceinline__ void ldsm_x4_t(unsigned* r, unsigned addr) {
    asm volatile("ldmatrix.sync.aligned.m8n8.x4.trans.shared.b16 {%0,%1,%2,%3}, [%4];"
        : "=r"(r[0]), "=r"(r[1]), "=r"(r[2]), "=r"(r[3]) : "r"(addr));
}
__device__ __forceinline__ void mma_f16(float* c, const unsigned* a, const unsigned* b) {
    asm volatile("mma.sync.aligned.m16n8k16.row.col.f32.f16.f16.f32 "
        "{%0,%1,%2,%3}, {%4,%5,%6,%7}, {%8,%9}, {%0,%1,%2,%3};"
        : "+f"(c[0]), "+f"(c[1]), "+f"(c[2]), "+f"(c[3])
        : "r"(a[0]), "r"(a[1]), "r"(a[2]), "r"(a[3]), "r"(b[0]), "r"(b[1]));
}
__device__ __forceinline__ void cp16(unsigned dst, const void* src, int pred_bytes) {
    asm volatile("cp.async.cg.shared.global [%0], [%1], 16, %2;"
        :: "r"(dst), "l"(src), "r"(pred_bytes) : "memory");
}
#define CP_COMMIT() asm volatile("cp.async.commit_group;" ::: "memory")
#define CP_WAIT0()  asm volatile("cp.async.wait_group 0;" ::: "memory")

// ---------------- capnorm x -> g_xn (fp32) + g_xh (fp16) ----------------
__global__ void capnorm_k(const float* __restrict__ in) {
    if (!in) return;                                   // warmup guard
    int idx = blockIdx.x * blockDim.x + threadIdx.x;   // (row, group of 16)
    if (idx >= N_NODES * KCAPS) return;
    const float4* p = (const float4*)(in + (size_t)idx * 16);
    float v[16];
    #pragma unroll
    for (int q = 0; q < 4; q++) {
        float4 t = p[q];
        v[q*4+0]=t.x; v[q*4+1]=t.y; v[q*4+2]=t.z; v[q*4+3]=t.w;
    }
    float n2 = 0.f;
    #pragma unroll
    for (int j = 0; j < 16; j++) n2 += v[j]*v[j];
    float inv = 1.0f / fmaxf(sqrtf(n2), EPS);
    #pragma unroll
    for (int j = 0; j < 16; j++) v[j] *= inv;
    float4* q4 = (float4*)(g_xn + (size_t)idx * 16);
    #pragma unroll
    for (int q = 0; q < 4; q++)
        q4[q] = make_float4(v[q*4], v[q*4+1], v[q*4+2], v[q*4+3]);
    unsigned hu[8];
    #pragma unroll
    for (int j = 0; j < 8; j++)
        hu[j] = pack_h2(__float2half_rn(v[2*j]), __float2half_rn(v[2*j+1]));
    uint4* dh = (uint4*)(g_xh + (size_t)idx * 16);
    dh[0] = make_uint4(hu[0],hu[1],hu[2],hu[3]);
    dh[1] = make_uint4(hu[4],hu[5],hu[6],hu[7]);
}

// ---------------- fp16 GEMM: A reg-staged+converted, B via cp.async ----------------
__device__ __forceinline__ void ldg_A(const float* __restrict__ A, int t, int tid,
                                      int blockRow, float4* a) {
    int arow = blockRow + (tid >> 2);
    int akc  = (tid & 3) * 16;
    int k0   = t * BK;
    const float* base = A + (size_t)arow * N_NODES;
    #pragma unroll
    for (int i = 0; i < 4; i++) {
        int kk = k0 + akc + i * 4;
        a[i] = (arow < N_EDGES && kk + 4 <= N_NODES)
             ? *(const float4*)(base + kk) : make_float4(0,0,0,0);
    }
}

__device__ __forceinline__ void sts_A(__half* stage, int tid, const float4* a) {
    float f[16];
    #pragma unroll
    for (int i = 0; i < 4; i++) {
        f[i*4+0]=a[i].x; f[i*4+1]=a[i].y; f[i*4+2]=a[i].z; f[i*4+3]=a[i].w;
    }
    unsigned hu[8];
    #pragma unroll
    for (int i = 0; i < 8; i++)
        hu[i] = pack_h2(__float2half_rn(f[2*i]), __float2half_rn(f[2*i+1]));
    int ar = tid >> 2, akc = (tid & 3) * 16;
    *(uint4*)(stage + ar*RSA + akc)     = make_uint4(hu[0],hu[1],hu[2],hu[3]);
    *(uint4*)(stage + ar*RSA + akc + 8) = make_uint4(hu[4],hu[5],hu[6],hu[7]);
}

__device__ __forceinline__ void cp_B(__half* stage, int t, int tid) {
    int br = tid >> 2, bn = (tid & 3) * 32;
    int brow = t * BK + br;
    int ok = (brow < N_NODES) ? 16 : 0;
    const __half* src = g_xh + (size_t)(brow < N_NODES ? brow : 0) * DIM + bn;
    unsigned dst = (unsigned)__cvta_generic_to_shared(stage + BM*RSA + br*RSB + bn);
    #pragma unroll
    for (int i = 0; i < 4; i++)
        cp16(dst + i*16, src + i*8, ok);
}

extern __shared__ __half g_smem[];

__global__ void __launch_bounds__(256, 2) gemm_f16_k(const float* __restrict__ A) {
    if (!A) return;                                    // warmup guard (uniform)
    int tid = threadIdx.x;
    int split = blockIdx.y;
    int blockRow = blockIdx.x * BM;
    int t0 = (split * TILES) / NSPLIT;
    int t1 = ((split + 1) * TILES) / NSPLIT;

    int lane = tid & 31, wid = tid >> 5;
    int wm = wid & 1, wn = wid >> 1;          // 2 M-warps x 4 N-warps
    int m_off = wm * 32, n_off = wn * 32;

    float c[8][4];
    #pragma unroll
    for (int i = 0; i < 8; i++)
        #pragma unroll
        for (int j = 0; j < 4; j++) c[i][j] = 0.f;

    float4 areg[4];
    ldg_A(A, t0, tid, blockRow, areg);
    cp_B(g_smem, t0, tid);
    CP_COMMIT();
    sts_A(g_smem, tid, areg);
    CP_WAIT0();
    __syncthreads();

    int g = lane >> 3, rr = lane & 7;
    int aoff = ((g & 1) ? 8 : 0) + rr;
    int akx  = ((g & 2) ? 8 : 0);
    int boff = ((g & 1) ? 8 : 0) + rr;
    int bnx  = ((g & 2) ? 8 : 0);

    for (int t = t0; t < t1; t++) {
        __half* cur = g_smem + ((t - t0) & 1) * STAGE_ELEMS;
        __half* nxt = g_smem + (((t - t0) + 1) & 1) * STAGE_ELEMS;
        bool have_next = (t + 1 < t1);
        if (have_next) {
            ldg_A(A, t + 1, tid, blockRow, areg);
            cp_B(nxt, t + 1, tid);
            CP_COMMIT();
        }

        __half* As = cur;
        __half* Bs = cur + BM*RSA;

        #pragma unroll
        for (int ks = 0; ks < 4; ks++) {
            int k0 = ks * 16;
            unsigned af[2][4], bf[8];
            #pragma unroll
            for (int mf = 0; mf < 2; mf++) {
                int mrow = m_off + mf*16 + aoff;
                ldsm_x4(af[mf], (unsigned)__cvta_generic_to_shared(As + mrow*RSA + k0 + akx));
            }
            #pragma unroll
            for (int nf = 0; nf < 2; nf++) {
                int ncol = n_off + nf*16 + bnx;
                ldsm_x4_t(&bf[nf*4], (unsigned)__cvta_generic_to_shared(Bs + (k0 + boff)*RSB + ncol));
            }
            #pragma unroll
            for (int mf = 0; mf < 2; mf++) {
                #pragma unroll
                for (int j = 0; j < 4; j++) {
                    const unsigned* bb = &bf[(j >> 1)*4 + (j & 1)*2];
                    mma_f16(c[mf*4+j], af[mf], bb);
                }
            }
        }
        if (have_next) sts_A(nxt, tid, areg);
        CP_WAIT0();
        __syncthreads();
    }

    float* out = g_gpart[split];
    #pragma unroll
    for (int mf = 0; mf < 2; mf++) {
        #pragma unroll
        for (int j = 0; j < 4; j++) {
            int n  = n_off + j*8 + (lane & 3)*2;
            int r1 = blockRow + m_off + mf*16 + (lane >> 2);
            int r2 = r1 + 8;
            float* cc = c[mf*4+j];
            if (r1 < N_EDGES) *(float2*)(out + (size_t)r1*DIM + n) = make_float2(cc[0], cc[1]);
            if (r2 < N_EDGES) *(float2*)(out + (size_t)r2*DIM + n) = make_float2(cc[2], cc[3]);
        }
    }
}

// ---------------- CSR build (fused) ----------------
__global__ void zero_cnt_k() {
    int i = blockIdx.x * blockDim.x + threadIdx.x;
    if (i < N_EDGES) g_cntE[i] = 0;
    if (i < N_NODES) g_cntN[i] = 0;
}

__global__ void hist_k(const int* __restrict__ edge_es, const int* __restrict__ node_es) {
    if (!edge_es) return;                              // warmup guard
    int i = blockIdx.x * blockDim.x + threadIdx.x;
    if (i >= M_PAIRS) return;
    atomicAdd(&g_cntE[edge_es[i]], 1);
    atomicAdd(&g_cntN[node_es[i]], 1);
}

__global__ void scan_both_k(int active) {
    if (!active) return;                               // warmup guard (uniform)
    const int* cnt;  int* start;  int* wptr;  int n;
    if (blockIdx.x == 0) { cnt = g_cntE; start = g_startE; wptr = g_wptrE; n = N_EDGES; }
    else                 { cnt = g_cntN; start = g_startN; wptr = g_wptrN; n = N_NODES; }
    __shared__ int ssum[1024];
    int t = threadIdx.x;
    int CH = (n + 1023) / 1024;
    int s0 = t * CH;
    int s = 0;
    for (int i = 0; i < CH; i++) { int j = s0 + i; if (j < n) s += cnt[j]; }
    ssum[t] = s;
    __syncthreads();
    for (int off = 1; off < 1024; off <<= 1) {
        int v = (t >= off) ? ssum[t - off] : 0;
        __syncthreads();
        ssum[t] += v;
        __syncthreads();
    }
    int run = (t > 0) ? ssum[t - 1] : 0;
    for (int i = 0; i < CH; i++) {
        int j = s0 + i;
        if (j < n) { start[j] = run; wptr[j] = run; run += cnt[j]; }
    }
    if (t == 0) start[n] = M_PAIRS;
}

__global__ void scatter_both_k(const int* __restrict__ edge_es, const int* __restrict__ node_es) {
    if (!edge_es) return;                              // warmup guard
    int i = blockIdx.x * blockDim.x + threadIdx.x;
    if (i >= M_PAIRS) return;
    int e = edge_es[i], nn = node_es[i];
    int posE = atomicAdd(&g_wptrE[e], 1);
    g_tmpE[posE] = make_int2(nn, i);
    int posN = atomicAdd(&g_wptrN[nn], 1);
    g_tmpN[posN] = make_int2(e, i);
}

__global__ void reorder_both_k(int active) {
    if (!active) return;                               // warmup guard
    int warp = (blockIdx.x * blockDim.x + threadIdx.x) >> 5;
    int lane = threadIdx.x & 31;
    const int2* tmp; const int* start; int2* out; int run;
    if (warp < N_EDGES) { tmp = g_tmpE; start = g_startE; out = g_itemsE; run = warp; }
    else if (warp < N_EDGES + N_NODES) {
        tmp = g_tmpN; start = g_startN; out = g_itemsN; run = warp - N_EDGES;
    } else return;
    int s = start[run], e = start[run + 1];
    for (int i = s + lane; i < e; i += 32) {
        int2 my = tmp[i];
        int rank = 0;
        for (int j = s; j < e; j++) rank += (tmp[j].y < my.y);
        out[s + rank] = my;
    }
}

// ---------------- routing: one warp per dst row, u in registers (R9 form) ----------------
// MODE 1: fold = orig_pos / FOLD_LEN. MODE 2: fold = csr_pos / FOLD_LEN.
// SUMP: init u from NSPLIT split-K partials (sum + capnorm in-warp).
template <int MODE, bool SUMP>
__global__ void routing_k(const float* __restrict__ uinit, const float* __restrict__ src,
                          const int* __restrict__ start, const int2* __restrict__ items,
                          float* __restrict__ out, float* __restrict__ out2, int nrows) {
    int warp = (blockIdx.x * blockDim.x + threadIdx.x) >> 5;
    int lane = threadIdx.x & 31;
    if (warp >= nrows) return;                         // nrows=0 during warmup
    int row = warp;
    const unsigned FULL = 0xFFFFFFFFu;

    float4 u;
    if (SUMP) {
        u = make_float4(0.f, 0.f, 0.f, 0.f);
        #pragma unroll
        for (int p = 0; p < NSPLIT; p++) {
            float4 t = *(const float4*)(uinit + (size_t)p * N_EDGES * DIM
                                        + (size_t)row * DIM + lane * 4);
            u.x += t.x; u.y += t.y; u.z += t.z; u.w += t.w;
        }
        float n2 = u.x*u.x + u.y*u.y + u.z*u.z + u.w*u.w;
        n2 += __shfl_xor_sync(FULL, n2, 1);
        n2 += __shfl_xor_sync(FULL, n2, 2);
        float inv = 1.0f / fmaxf(sqrtf(n2), EPS);
        u.x *= inv; u.y *= inv; u.z *= inv; u.w *= inv;
    } else {
        u = *(const float4*)(uinit + (size_t)row * DIM + lane * 4);
    }

    int s = start[row], e = start[row + 1];

    for (int iter = 0; iter < 2; iter++) {
        float4 acc = make_float4(0.f, 0.f, 0.f, 0.f);
        int curfold = -1;
        int2 it = make_int2(0, 0);
        float4 z = make_float4(0.f, 0.f, 0.f, 0.f);
        if (s < e) {
            it = items[s];
            z = *(const float4*)(src + (size_t)it.x * DIM + lane * 4);
        }
        for (int i = s; i < e; i++) {
            // prefetch NEXT item's z row (off critical path)
            int2 itn = it; float4 zn = z;
            if (i + 1 < e) {
                itn = items[i + 1];
                zn = *(const float4*)(src + (size_t)itn.x * DIM + lane * 4);
            }
            int fold = (MODE == 1) ? (it.y / FOLD_LEN) : (i / FOLD_LEN);
            if (fold != curfold) {
                if (curfold >= 0) {
                    u.x += acc.x; u.y += acc.y; u.z += acc.z; u.w += acc.w;
                    acc = make_float4(0.f, 0.f, 0.f, 0.f);
                }
                curfold = fold;
            }
            float d = z.x*u.x + z.y*u.y + z.z*u.z + z.w*u.w;
            d += __shfl_xor_sync(FULL, d, 1);
            d += __shfl_xor_sync(FULL, d, 2);
            // softmax without max-subtraction: |d| <= 1+run_len << 88, no overflow
            float ex = __expf(d);
            float se = ex;
            se += __shfl_xor_sync(FULL, se, 4);
            se += __shfl_xor_sync(FULL, se, 8);
            se += __shfl_xor_sync(FULL, se, 16);
            float pr = __fdividef(ex, se);
            acc.x += z.x * pr; acc.y += z.y * pr; acc.z += z.z * pr; acc.w += z.w * pr;
            it = itn; z = zn;
        }
        u.x += acc.x; u.y += acc.y; u.z += acc.z; u.w += acc.w;
        float n2 = u.x*u.x + u.y*u.y + u.z*u.z + u.w*u.w;
        n2 += __shfl_xor_sync(FULL, n2, 1);
        n2 += __shfl_xor_sync(FULL, n2, 2);
        float inv = 1.0f / fmaxf(sqrtf(n2), EPS);
        u.x *= inv; u.y *= inv; u.z *= inv; u.w *= inv;
    }

    *(float4*)(out + (size_t)row * DIM + lane * 4) = u;
    if (out2) *(float4*)(out2 + (size_t)row * DIM + lane * 4) = u;
}

// ---------------- pre-main warmup ----------------
static float *p_xn, *p_gpart, *p_uedge;
static int   *p_startE, *p_startN;
static int2  *p_itemsE, *p_itemsN;
static cudaStream_t s2;
static cudaEvent_t evFork, evJoin;

namespace {
struct Warmup {
    Warmup() {
        cudaGetSymbolAddress((void**)&p_xn, g_xn);
        cudaGetSymbolAddress((void**)&p_gpart, g_gpart);
        cudaGetSymbolAddress((void**)&p_uedge, g_uedge);
        cudaGetSymbolAddress((void**)&p_startE, g_startE);
        cudaGetSymbolAddress((void**)&p_startN, g_startN);
        cudaGetSymbolAddress((void**)&p_itemsE, g_itemsE);
        cudaGetSymbolAddress((void**)&p_itemsN, g_itemsN);

        cudaStreamCreateWithFlags(&s2, cudaStreamNonBlocking);
        cudaEventCreateWithFlags(&evFork, cudaEventDisableTiming);
        cudaEventCreateWithFlags(&evJoin, cudaEventDisableTiming);

        cudaFuncSetAttribute(gemm_f16_k, cudaFuncAttributeMaxDynamicSharedMemorySize,
                             GEMM_SMEM_BYTES);

        // Warm-launch every kernel with inert arguments.
        capnorm_k<<<1, 256>>>((const float*)0);
        gemm_f16_k<<<dim3(1, 1), 256, GEMM_SMEM_BYTES>>>((const float*)0);
        zero_cnt_k<<<1, 256, 0, s2>>>();
        hist_k<<<1, 256, 0, s2>>>((const int*)0, (const int*)0);
        scan_both_k<<<2, 1024, 0, s2>>>(0);
        scatter_both_k<<<1, 256, 0, s2>>>((const int*)0, (const int*)0);
        reorder_both_k<<<1, 256, 0, s2>>>(0);
        routing_k<1, true><<<1, 256>>>((const float*)0, (const float*)0, (const int*)0,
                                       (const int2*)0, (float*)0, (float*)0, 0);
        routing_k<2, false><<<1, 256>>>((const float*)0, (const float*)0, (const int*)0,
                                        (const int2*)0, (float*)0, (float*)0, 0);
        cudaDeviceSynchronize();
    }
};
static Warmup _warmup;
}

// ---------------- launch: pure kernel launches + capturable fork/join ----------------
extern "C" void kernel_launch(void* const* d_in, const int* in_sizes, int n_in,
                              void* d_out, int out_size) {
    const float* x   = (const float*)d_in[0];
    const float* adj = (const float*)d_in[1];
    const int*   en  = (const int*)d_in[2];
    const int* edge_es = en;            // edge_node[0]
    const int* node_es = en + M_PAIRS;  // edge_node[1]

    float* out_node = (float*)d_out;                       // u_node_all
    float* out_edge = out_node + (size_t)N_NODES * DIM;    // u_edge_all

    // ---- fork: CSR chain on s2, concurrent with GEMM chain ----
    cudaEventRecord(evFork, 0);
    cudaStreamWaitEvent(s2, evFork, 0);
    zero_cnt_k<<<(N_NODES + 255) / 256, 256, 0, s2>>>();
    hist_k<<<(M_PAIRS + 255) / 256, 256, 0, s2>>>(edge_es, node_es);
    scan_both_k<<<2, 1024, 0, s2>>>(1);
    scatter_both_k<<<(M_PAIRS + 255) / 256, 256, 0, s2>>>(edge_es, node_es);
    reorder_both_k<<<((N_EDGES + N_NODES) * 32 + 255) / 256, 256, 0, s2>>>(1);
    cudaEventRecord(evJoin, s2);

    // ---- main chain: capnorm -> fp16 GEMM (split-K=7, 553 CTAs = 2 clean waves) ----
    capnorm_k<<<(N_NODES * KCAPS + 255) / 256, 256>>>(x);
    dim3 ggrid((N_EDGES + BM - 1) / BM, NSPLIT);
    gemm_f16_k<<<ggrid, 256, GEMM_SMEM_BYTES>>>(adj);

    // ---- join, then routing (R9 form; routing1 fuses split-K sum + capnorm) ----
    cudaStreamWaitEvent(0, evJoin, 0);
    routing_k<1, true><<<(N_EDGES + 7) / 8, 256>>>(p_gpart, p_xn, p_startE, p_itemsE,
                                                   p_uedge, out_edge, N_EDGES);
    routing_k<2, false><<<(N_NODES + 7) / 8, 256>>>(p_xn, p_uedge, p_startN, p_itemsN,
                                                    out_node, (float*)0, N_NODES);
}

// round 15
// speedup vs baseline: 1.1266x; 1.0039x over previous
#include <cuda_runtime.h>
#include <cuda_fp16.h>
#include <math.h>
#include <stdint.h>

#define N_NODES 10000
#define N_EDGES 5000
#define M_PAIRS 200000
#define DIM 128
#define KCAPS 8
#define FOLD_LEN 10000   // M / NFOLD
#define NSPLIT 7         // 79 row-blocks x 7 = 553 CTAs: 296+257 = 2 clean waves
#define EPS 1e-12f

// GEMM tiling (fp16 single-pass)
#define BM 64
#define BK 64
#define TILES 157            // ceil(10000/64)
#define RSA 72               // A smem row stride (fp16), padded
#define RSB 136              // B smem row stride (fp16), padded
#define STAGE_ELEMS (BM*RSA + BK*RSB)          // 13312 fp16 per stage
#define GEMM_SMEM_BYTES (2 * STAGE_ELEMS * 2)  // 53248 B -> 2 CTAs/SM

// ---------------- scratch (static device globals; no allocation) ----------------
__device__ float  g_xn[N_NODES * DIM];                // capnormed x (fp32)
__device__ __half g_xh[N_NODES * DIM];                // capnormed x (fp16)
__device__ float  g_gpart[NSPLIT][N_EDGES * DIM];     // split-K GEMM partials
__device__ float  g_uedge[N_EDGES * DIM];             // routing1 result

__device__ int  g_cntE[N_EDGES],  g_startE[N_EDGES + 1],  g_wptrE[N_EDGES];
__device__ int  g_cntN[N_NODES],  g_startN[N_NODES + 1],  g_wptrN[N_NODES];
__device__ int2 g_tmpE[M_PAIRS],  g_itemsE[M_PAIRS];
__device__ int2 g_tmpN[M_PAIRS],  g_itemsN[M_PAIRS];

// ---------------- small helpers ----------------
__device__ __forceinline__ unsigned pack_h2(__half lo, __half hi) {
    return ((unsigned)__half_as_ushort(hi) << 16) | (unsigned)__half_as_ushort(lo);
}
__device__ __forceinline__ void ldsm_x4(unsigned* r, unsigned addr) {
    asm volatile("ldmatrix.sync.aligned.m8n8.x4.shared.b16 {%0,%1,%2,%3}, [%4];"
        : "=r"(r[0]), "=r"(r[1]), "=r"(r[2]), "=r"(r[3]) : "r"(addr));
}
__device__ __forceinline__ void ldsm_x4_t(unsigned* r, unsigned addr) {
    asm volatile("ldmatrix.sync.aligned.m8n8.x4.trans.shared.b16 {%0,%1,%2,%3}, [%4];"
        : "=r"(r[0]), "=r"(r[1]), "=r"(r[2]), "=r"(r[3]) : "r"(addr));
}
__device__ __forceinline__ void mma_f16(float* c, const unsigned* a, const unsigned* b) {
    asm volatile("mma.sync.aligned.m16n8k16.row.col.f32.f16.f16.f32 "
        "{%0,%1,%2,%3}, {%4,%5,%6,%7}, {%8,%9}, {%0,%1,%2,%3};"
        : "+f"(c[0]), "+f"(c[1]), "+f"(c[2]), "+f"(c[3])
        : "r"(a[0]), "r"(a[1]), "r"(a[2]), "r"(a[3]), "r"(b[0]), "r"(b[1]));
}
__device__ __forceinline__ void cp16(unsigned dst, const void* src, int pred_bytes) {
    asm volatile("cp.async.cg.shared.global [%0], [%1], 16, %2;"
        :: "r"(dst), "l"(src), "r"(pred_bytes) : "memory");
}
#define CP_COMMIT() asm volatile("cp.async.commit_group;" ::: "memory")
#define CP_WAIT0()  asm volatile("cp.async.wait_group 0;" ::: "memory")

// ---------------- capnorm x -> g_xn (fp32) + g_xh (fp16) ----------------
__global__ void capnorm_k(const float* __restrict__ in) {
    if (!in) return;                                   // warmup guard
    int idx = blockIdx.x * blockDim.x + threadIdx.x;   // (row, group of 16)
    if (idx >= N_NODES * KCAPS) return;
    const float4* p = (const float4*)(in + (size_t)idx * 16);
    float v[16];
    #pragma unroll
    for (int q = 0; q < 4; q++) {
        float4 t = p[q];
        v[q*4+0]=t.x; v[q*4+1]=t.y; v[q*4+2]=t.z; v[q*4+3]=t.w;
    }
    float n2 = 0.f;
    #pragma unroll
    for (int j = 0; j < 16; j++) n2 += v[j]*v[j];
    float inv = 1.0f / fmaxf(sqrtf(n2), EPS);
    #pragma unroll
    for (int j = 0; j < 16; j++) v[j] *= inv;
    float4* q4 = (float4*)(g_xn + (size_t)idx * 16);
    #pragma unroll
    for (int q = 0; q < 4; q++)
        q4[q] = make_float4(v[q*4], v[q*4+1], v[q*4+2], v[q*4+3]);
    unsigned hu[8];
    #pragma unroll
    for (int j = 0; j < 8; j++)
        hu[j] = pack_h2(__float2half_rn(v[2*j]), __float2half_rn(v[2*j+1]));
    uint4* dh = (uint4*)(g_xh + (size_t)idx * 16);
    dh[0] = make_uint4(hu[0],hu[1],hu[2],hu[3]);
    dh[1] = make_uint4(hu[4],hu[5],hu[6],hu[7]);
}

// ---------------- fp16 GEMM: A reg-staged+converted, B via cp.async ----------------
__device__ __forceinline__ void ldg_A(const float* __restrict__ A, int t, int tid,
                                      int blockRow, float4* a) {
    int arow = blockRow + (tid >> 2);
    int akc  = (tid & 3) * 16;
    int k0   = t * BK;
    const float* base = A + (size_t)arow * N_NODES;
    #pragma unroll
    for (int i = 0; i < 4; i++) {
        int kk = k0 + akc + i * 4;
        a[i] = (arow < N_EDGES && kk + 4 <= N_NODES)
             ? *(const float4*)(base + kk) : make_float4(0,0,0,0);
    }
}

__device__ __forceinline__ void sts_A(__half* stage, int tid, const float4* a) {
    float f[16];
    #pragma unroll
    for (int i = 0; i < 4; i++) {
        f[i*4+0]=a[i].x; f[i*4+1]=a[i].y; f[i*4+2]=a[i].z; f[i*4+3]=a[i].w;
    }
    unsigned hu[8];
    #pragma unroll
    for (int i = 0; i < 8; i++)
        hu[i] = pack_h2(__float2half_rn(f[2*i]), __float2half_rn(f[2*i+1]));
    int ar = tid >> 2, akc = (tid & 3) * 16;
    *(uint4*)(stage + ar*RSA + akc)     = make_uint4(hu[0],hu[1],hu[2],hu[3]);
    *(uint4*)(stage + ar*RSA + akc + 8) = make_uint4(hu[4],hu[5],hu[6],hu[7]);
}

__device__ __forceinline__ void cp_B(__half* stage, int t, int tid) {
    int br = tid >> 2, bn = (tid & 3) * 32;
    int brow = t * BK + br;
    int ok = (brow < N_NODES) ? 16 : 0;
    const __half* src = g_xh + (size_t)(brow < N_NODES ? brow : 0) * DIM + bn;
    unsigned dst = (unsigned)__cvta_generic_to_shared(stage + BM*RSA + br*RSB + bn);
    #pragma unroll
    for (int i = 0; i < 4; i++)
        cp16(dst + i*16, src + i*8, ok);
}

extern __shared__ __half g_smem[];

__global__ void __launch_bounds__(256, 2) gemm_f16_k(const float* __restrict__ A) {
    if (!A) return;                                    // warmup guard (uniform)
    int tid = threadIdx.x;
    int split = blockIdx.y;
    int blockRow = blockIdx.x * BM;
    int t0 = (split * TILES) / NSPLIT;
    int t1 = ((split + 1) * TILES) / NSPLIT;

    int lane = tid & 31, wid = tid >> 5;
    int wm = wid & 1, wn = wid >> 1;          // 2 M-warps x 4 N-warps
    int m_off = wm * 32, n_off = wn * 32;

    float c[8][4];
    #pragma unroll
    for (int i = 0; i < 8; i++)
        #pragma unroll
        for (int j = 0; j < 4; j++) c[i][j] = 0.f;

    float4 areg[4];
    ldg_A(A, t0, tid, blockRow, areg);
    cp_B(g_smem, t0, tid);
    CP_COMMIT();
    sts_A(g_smem, tid, areg);
    CP_WAIT0();
    __syncthreads();

    int g = lane >> 3, rr = lane & 7;
    int aoff = ((g & 1) ? 8 : 0) + rr;
    int akx  = ((g & 2) ? 8 : 0);
    int boff = ((g & 1) ? 8 : 0) + rr;
    int bnx  = ((g & 2) ? 8 : 0);

    for (int t = t0; t < t1; t++) {
        __half* cur = g_smem + ((t - t0) & 1) * STAGE_ELEMS;
        __half* nxt = g_smem + (((t - t0) + 1) & 1) * STAGE_ELEMS;
        bool have_next = (t + 1 < t1);
        if (have_next) {
            ldg_A(A, t + 1, tid, blockRow, areg);
            cp_B(nxt, t + 1, tid);
            CP_COMMIT();
        }

        __half* As = cur;
        __half* Bs = cur + BM*RSA;

        #pragma unroll
        for (int ks = 0; ks < 4; ks++) {
            int k0 = ks * 16;
            unsigned af[2][4], bf[8];
            #pragma unroll
            for (int mf = 0; mf < 2; mf++) {
                int mrow = m_off + mf*16 + aoff;
                ldsm_x4(af[mf], (unsigned)__cvta_generic_to_shared(As + mrow*RSA + k0 + akx));
            }
            #pragma unroll
            for (int nf = 0; nf < 2; nf++) {
                int ncol = n_off + nf*16 + bnx;
                ldsm_x4_t(&bf[nf*4], (unsigned)__cvta_generic_to_shared(Bs + (k0 + boff)*RSB + ncol));
            }
            #pragma unroll
            for (int mf = 0; mf < 2; mf++) {
                #pragma unroll
                for (int j = 0; j < 4; j++) {
                    const unsigned* bb = &bf[(j >> 1)*4 + (j & 1)*2];
                    mma_f16(c[mf*4+j], af[mf], bb);
                }
            }
        }
        if (have_next) sts_A(nxt, tid, areg);
        CP_WAIT0();
        __syncthreads();
    }

    float* out = g_gpart[split];
    #pragma unroll
    for (int mf = 0; mf < 2; mf++) {
        #pragma unroll
        for (int j = 0; j < 4; j++) {
            int n  = n_off + j*8 + (lane & 3)*2;
            int r1 = blockRow + m_off + mf*16 + (lane >> 2);
            int r2 = r1 + 8;
            float* cc = c[mf*4+j];
            if (r1 < N_EDGES) *(float2*)(out + (size_t)r1*DIM + n) = make_float2(cc[0], cc[1]);
            if (r2 < N_EDGES) *(float2*)(out + (size_t)r2*DIM + n) = make_float2(cc[2], cc[3]);
        }
    }
}

// ---------------- CSR build (fused) ----------------
__global__ void zero_cnt_k() {
    int i = blockIdx.x * blockDim.x + threadIdx.x;
    if (i < N_EDGES) g_cntE[i] = 0;
    if (i < N_NODES) g_cntN[i] = 0;
}

__global__ void hist_k(const int* __restrict__ edge_es, const int* __restrict__ node_es) {
    if (!edge_es) return;                              // warmup guard
    int i = blockIdx.x * blockDim.x + threadIdx.x;
    if (i >= M_PAIRS) return;
    atomicAdd(&g_cntE[edge_es[i]], 1);
    atomicAdd(&g_cntN[node_es[i]], 1);
}

__global__ void scan_both_k(int active) {
    if (!active) return;                               // warmup guard (uniform)
    const int* cnt;  int* start;  int* wptr;  int n;
    if (blockIdx.x == 0) { cnt = g_cntE; start = g_startE; wptr = g_wptrE; n = N_EDGES; }
    else                 { cnt = g_cntN; start = g_startN; wptr = g_wptrN; n = N_NODES; }
    __shared__ int ssum[1024];
    int t = threadIdx.x;
    int CH = (n + 1023) / 1024;
    int s0 = t * CH;
    int s = 0;
    for (int i = 0; i < CH; i++) { int j = s0 + i; if (j < n) s += cnt[j]; }
    ssum[t] = s;
    __syncthreads();
    for (int off = 1; off < 1024; off <<= 1) {
        int v = (t >= off) ? ssum[t - off] : 0;
        __syncthreads();
        ssum[t] += v;
        __syncthreads();
    }
    int run = (t > 0) ? ssum[t - 1] : 0;
    for (int i = 0; i < CH; i++) {
        int j = s0 + i;
        if (j < n) { start[j] = run; wptr[j] = run; run += cnt[j]; }
    }
    if (t == 0) start[n] = M_PAIRS;
}

__global__ void scatter_both_k(const int* __restrict__ edge_es, const int* __restrict__ node_es) {
    if (!edge_es) return;                              // warmup guard
    int i = blockIdx.x * blockDim.x + threadIdx.x;
    if (i >= M_PAIRS) return;
    int e = edge_es[i], nn = node_es[i];
    int posE = atomicAdd(&g_wptrE[e], 1);
    g_tmpE[posE] = make_int2(nn, i);
    int posN = atomicAdd(&g_wptrN[nn], 1);
    g_tmpN[posN] = make_int2(e, i);
}

__global__ void reorder_both_k(int active) {
    if (!active) return;                               // warmup guard
    int warp = (blockIdx.x * blockDim.x + threadIdx.x) >> 5;
    int lane = threadIdx.x & 31;
    const int2* tmp; const int* start; int2* out; int run;
    if (warp < N_EDGES) { tmp = g_tmpE; start = g_startE; out = g_itemsE; run = warp; }
    else if (warp < N_EDGES + N_NODES) {
        tmp = g_tmpN; start = g_startN; out = g_itemsN; run = warp - N_EDGES;
    } else return;
    int s = start[run], e = start[run + 1];
    for (int i = s + lane; i < e; i += 32) {
        int2 my = tmp[i];
        int rank = 0;
        for (int j = s; j < e; j++) rank += (tmp[j].y < my.y);
        out[s + rank] = my;
    }
}

// ---------------- routing: one warp per dst row, u in registers (R9 form) ----------------
// MODE 1: fold = orig_pos / FOLD_LEN. MODE 2: fold = csr_pos / FOLD_LEN.
// SUMP: init u from NSPLIT split-K partials (sum + capnorm in-warp).
template <int MODE, bool SUMP>
__global__ void routing_k(const float* __restrict__ uinit, const float* __restrict__ src,
                          const int* __restrict__ start, const int2* __restrict__ items,
                          float* __restrict__ out, float* __restrict__ out2, int nrows) {
    int warp = (blockIdx.x * blockDim.x + threadIdx.x) >> 5;
    int lane = threadIdx.x & 31;
    if (warp >= nrows) return;                         // nrows=0 during warmup
    int row = warp;
    const unsigned FULL = 0xFFFFFFFFu;

    float4 u;
    if (SUMP) {
        u = make_float4(0.f, 0.f, 0.f, 0.f);
        #pragma unroll
        for (int p = 0; p < NSPLIT; p++) {
            float4 t = *(const float4*)(uinit + (size_t)p * N_EDGES * DIM
                                        + (size_t)row * DIM + lane * 4);
            u.x += t.x; u.y += t.y; u.z += t.z; u.w += t.w;
        }
        float n2 = u.x*u.x + u.y*u.y + u.z*u.z + u.w*u.w;
        n2 += __shfl_xor_sync(FULL, n2, 1);
        n2 += __shfl_xor_sync(FULL, n2, 2);
        float inv = 1.0f / fmaxf(sqrtf(n2), EPS);
        u.x *= inv; u.y *= inv; u.z *= inv; u.w *= inv;
    } else {
        u = *(const float4*)(uinit + (size_t)row * DIM + lane * 4);
    }

    int s = start[row], e = start[row + 1];

    for (int iter = 0; iter < 2; iter++) {
        float4 acc = make_float4(0.f, 0.f, 0.f, 0.f);
        int curfold = -1;
        int2 it = make_int2(0, 0);
        float4 z = make_float4(0.f, 0.f, 0.f, 0.f);
        if (s < e) {
            it = items[s];
            z = *(const float4*)(src + (size_t)it.x * DIM + lane * 4);
        }
        for (int i = s; i < e; i++) {
            // prefetch NEXT item's z row (off critical path)
            int2 itn = it; float4 zn = z;
            if (i + 1 < e) {
                itn = items[i + 1];
                zn = *(const float4*)(src + (size_t)itn.x * DIM + lane * 4);
            }
            int fold = (MODE == 1) ? (it.y / FOLD_LEN) : (i / FOLD_LEN);
            if (fold != curfold) {
                if (curfold >= 0) {
                    u.x += acc.x; u.y += acc.y; u.z += acc.z; u.w += acc.w;
                    acc = make_float4(0.f, 0.f, 0.f, 0.f);
                }
                curfold = fold;
            }
            float d = z.x*u.x + z.y*u.y + z.z*u.z + z.w*u.w;
            d += __shfl_xor_sync(FULL, d, 1);
            d += __shfl_xor_sync(FULL, d, 2);
            // softmax without max-subtraction: |d| <= 1+run_len << 88, no overflow
            float ex = __expf(d);
            float se = ex;
            se += __shfl_xor_sync(FULL, se, 4);
            se += __shfl_xor_sync(FULL, se, 8);
            se += __shfl_xor_sync(FULL, se, 16);
            float pr = __fdividef(ex, se);
            acc.x += z.x * pr; acc.y += z.y * pr; acc.z += z.z * pr; acc.w += z.w * pr;
            it = itn; z = zn;
        }
        u.x += acc.x; u.y += acc.y; u.z += acc.z; u.w += acc.w;
        float n2 = u.x*u.x + u.y*u.y + u.z*u.z + u.w*u.w;
        n2 += __shfl_xor_sync(FULL, n2, 1);
        n2 += __shfl_xor_sync(FULL, n2, 2);
        float inv = 1.0f / fmaxf(sqrtf(n2), EPS);
        u.x *= inv; u.y *= inv; u.z *= inv; u.w *= inv;
    }

    *(float4*)(out + (size_t)row * DIM + lane * 4) = u;
    if (out2) *(float4*)(out2 + (size_t)row * DIM + lane * 4) = u;
}

// ---------------- pre-main warmup ----------------
static float *p_xn, *p_gpart, *p_uedge;
static int   *p_startE, *p_startN;
static int2  *p_itemsE, *p_itemsN;
static cudaStream_t s2;
static cudaEvent_t evFork, evJoin;

namespace {
struct Warmup {
    Warmup() {
        cudaGetSymbolAddress((void**)&p_xn, g_xn);
        cudaGetSymbolAddress((void**)&p_gpart, g_gpart);
        cudaGetSymbolAddress((void**)&p_uedge, g_uedge);
        cudaGetSymbolAddress((void**)&p_startE, g_startE);
        cudaGetSymbolAddress((void**)&p_startN, g_startN);
        cudaGetSymbolAddress((void**)&p_itemsE, g_itemsE);
        cudaGetSymbolAddress((void**)&p_itemsN, g_itemsN);

        cudaStreamCreateWithFlags(&s2, cudaStreamNonBlocking);
        cudaEventCreateWithFlags(&evFork, cudaEventDisableTiming);
        cudaEventCreateWithFlags(&evJoin, cudaEventDisableTiming);

        cudaFuncSetAttribute(gemm_f16_k, cudaFuncAttributeMaxDynamicSharedMemorySize,
                             GEMM_SMEM_BYTES);

        // Warm-launch every kernel with inert arguments.
        capnorm_k<<<1, 256>>>((const float*)0);
        gemm_f16_k<<<dim3(1, 1), 256, GEMM_SMEM_BYTES>>>((const float*)0);
        zero_cnt_k<<<1, 256, 0, s2>>>();
        hist_k<<<1, 256, 0, s2>>>((const int*)0, (const int*)0);
        scan_both_k<<<2, 1024, 0, s2>>>(0);
        scatter_both_k<<<1, 256, 0, s2>>>((const int*)0, (const int*)0);
        reorder_both_k<<<1, 256, 0, s2>>>(0);
        routing_k<1, true><<<1, 256>>>((const float*)0, (const float*)0, (const int*)0,
                                       (const int2*)0, (float*)0, (float*)0, 0);
        routing_k<2, false><<<1, 256>>>((const float*)0, (const float*)0, (const int*)0,
                                        (const int2*)0, (float*)0, (float*)0, 0);
        cudaDeviceSynchronize();
    }
};
static Warmup _warmup;
}

// ---------------- launch: pure kernel launches + capturable fork/join ----------------
extern "C" void kernel_launch(void* const* d_in, const int* in_sizes, int n_in,
                              void* d_out, int out_size) {
    const float* x   = (const float*)d_in[0];
    const float* adj = (const float*)d_in[1];
    const int*   en  = (const int*)d_in[2];
    const int* edge_es = en;            // edge_node[0]
    const int* node_es = en + M_PAIRS;  // edge_node[1]

    float* out_node = (float*)d_out;                       // u_node_all
    float* out_edge = out_node + (size_t)N_NODES * DIM;    // u_edge_all

    // ---- fork: CSR chain on s2, concurrent with GEMM chain ----
    cudaEventRecord(evFork, 0);
    cudaStreamWaitEvent(s2, evFork, 0);
    zero_cnt_k<<<(N_NODES + 255) / 256, 256, 0, s2>>>();
    hist_k<<<(M_PAIRS + 255) / 256, 256, 0, s2>>>(edge_es, node_es);
    scan_both_k<<<2, 1024, 0, s2>>>(1);
    scatter_both_k<<<(M_PAIRS + 255) / 256, 256, 0, s2>>>(edge_es, node_es);
    reorder_both_k<<<((N_EDGES + N_NODES) * 32 + 255) / 256, 256, 0, s2>>>(1);
    cudaEventRecord(evJoin, s2);

    // ---- main chain: capnorm -> fp16 GEMM (split-K=7, 553 CTAs = 2 clean waves) ----
    capnorm_k<<<(N_NODES * KCAPS + 255) / 256, 256>>>(x);
    dim3 ggrid((N_EDGES + BM - 1) / BM, NSPLIT);
    gemm_f16_k<<<ggrid, 256, GEMM_SMEM_BYTES>>>(adj);

    // ---- join, then routing (R9 form; routing1 fuses split-K sum + capnorm) ----
    cudaStreamWaitEvent(0, evJoin, 0);
    routing_k<1, true><<<(N_EDGES + 7) / 8, 256>>>(p_gpart, p_xn, p_startE, p_itemsE,
                                                   p_uedge, out_edge, N_EDGES);
    routing_k<2, false><<<(N_NODES + 7) / 8, 256>>>(p_xn, p_uedge, p_startN, p_itemsN,
                                                    out_node, (float*)0, N_NODES);
}